// round 10
// baseline (speedup 1.0000x reference)
#include <cuda_runtime.h>
#include <cuda_bf16.h>
#include <math.h>
#include <stdint.h>

#define HDIM   1024
#define TSTEPS 256
#define VOCAB  50257

#define GRID_CTAS 148
#define THREADS   256

// ---------------- recurrence (R8 WIN design) ----------------
#define RNN_NB      64
#define VEC_PER_BLK 3
#define NVEC        (RNN_NB * VEC_PER_BLK)   // 192
#define VEC_STRIDE  8                        // 128B per vector

// ---------------- GEMM tiling ----------------
#define VBLKS  ((VOCAB + 127) / 128)         // 393
#define NTBLK  4
#define TBROWS (TSTEPS / NTBLK)              // 64
#define NTILES (VBLKS * NTBLK)               // 1572
#define TBK    32
#define PITCH  40                            // bf16 per smem row
#define A_TILE (128 * PITCH)
#define B_TILE (64 * PITCH)
#define STAGE  (A_TILE + B_TILE)             // 7680 bf16

#define FUSED_SMEM_BYTES (VOCAB * 4)         // 201028 B (covers softmax; >> gemm stages)

// -------- device scratch --------
__device__ __align__(16)  __nv_bfloat16 g_Hb[TSTEPS * HDIM];
__device__ __align__(128) uint4 g_pub[2 * NVEC * VEC_STRIDE];
__device__ __align__(128) unsigned g_prog[RNN_NB * 256];   // padded 1KB apart
__device__ __align__(128) unsigned g_done[NTBLK * 256];    // padded
__device__ unsigned g_qtile, g_qrow;

// ---- asm helpers
__device__ __forceinline__ uint4 ldv4u(const uint4* p) {
    uint4 v;
    asm volatile("ld.volatile.global.v4.u32 {%0,%1,%2,%3}, [%4];"
                 : "=r"(v.x), "=r"(v.y), "=r"(v.z), "=r"(v.w) : "l"(p));
    return v;
}
__device__ __forceinline__ void stv4u(uint4* p, uint4 v) {
    asm volatile("st.volatile.global.v4.u32 [%0], {%1,%2,%3,%4};"
                 :: "l"(p), "r"(v.x), "r"(v.y), "r"(v.z), "r"(v.w) : "memory");
}
__device__ __forceinline__ void st_release(unsigned* p, unsigned v) {
    asm volatile("st.release.gpu.u32 [%0], %1;" :: "l"(p), "r"(v) : "memory");
}
__device__ __forceinline__ unsigned ld_relaxed(const unsigned* p) {
    unsigned v;
    asm volatile("ld.relaxed.gpu.u32 %0, [%1];" : "=r"(v) : "l"(p) : "memory");
    return v;
}
__device__ __forceinline__ void fence_acqrel_gpu() {
    asm volatile("fence.acq_rel.gpu;" ::: "memory");
}
__device__ __forceinline__ void red_release_add(unsigned* p, unsigned v) {
    asm volatile("red.release.gpu.global.add.u32 [%0], %1;" :: "l"(p), "r"(v) : "memory");
}
__device__ __forceinline__ uint32_t pack_bf16(float lo, float hi) {
    __nv_bfloat162 v = __floats2bfloat162_rn(lo, hi);
    return *reinterpret_cast<uint32_t*>(&v);
}
__device__ __forceinline__ float bf16lo(uint32_t u) { return __uint_as_float(u << 16); }
__device__ __forceinline__ float bf16hi(uint32_t u) { return __uint_as_float(u & 0xFFFF0000u); }
__device__ __forceinline__ void cp16(uint32_t sdst, const void* gsrc) {
    asm volatile("cp.async.cg.shared.global [%0], [%1], 16;\n" :: "r"(sdst), "l"(gsrc));
}
__device__ __forceinline__ void cp_commit() { asm volatile("cp.async.commit_group;\n"); }
__device__ __forceinline__ void cp_wait0()  { asm volatile("cp.async.wait_group 0;\n"); }
__device__ __forceinline__ void mma_bf16(float d[4], const uint32_t a[4], const uint32_t b[2]) {
    asm volatile(
        "mma.sync.aligned.m16n8k16.row.col.f32.bf16.bf16.f32 "
        "{%0,%1,%2,%3}, {%4,%5,%6,%7}, {%8,%9}, {%0,%1,%2,%3};\n"
        : "+f"(d[0]), "+f"(d[1]), "+f"(d[2]), "+f"(d[3])
        : "r"(a[0]), "r"(a[1]), "r"(a[2]), "r"(a[3]), "r"(b[0]), "r"(b[1]));
}

// ---------------- init: reset all mutable state (graph-replay determinism)
__global__ void init_kernel() {
    int i = blockIdx.x * blockDim.x + threadIdx.x;
    if (i < 2 * NVEC) g_pub[i * VEC_STRIDE].w = 0u;
    if (i < RNN_NB)   g_prog[i * 256] = 0u;
    if (i < NTBLK)    g_done[i * 256] = 0u;
    if (i == 0) { g_qtile = 0u; g_qrow = 0u; }
}

// ============================================================================
// fused persistent kernel: 64 recurrence CTAs + 84 GEMM/softmax workers
// ============================================================================
extern __shared__ char smem_raw[];

__global__ void __launch_bounds__(THREADS, 1)
fused_kernel(const int* __restrict__ chars,
             const float* __restrict__ Wxh,
             const float* __restrict__ Whh,
             const float* __restrict__ Why,
             const float* __restrict__ bh,
             const float* __restrict__ by,
             const float* __restrict__ h0,
             float* __restrict__ out) {
    __shared__ float    sh[HDIM];
    __shared__ uint32_t hout_u[8];
    __shared__ int      s_chars[TSTEPS];
    __shared__ unsigned s_q;
    __shared__ float    red2[THREADS];

    const int bid  = blockIdx.x;
    const int tid  = threadIdx.x;
    const int wid  = tid >> 5;
    const int lane = tid & 31;

    // ======================= phase A: recurrence (CTAs 0..63) ===============
    if (bid < RNN_NB) {
        const int r0 = bid * 16 + wid * 2;
        const int r1 = r0 + 1;

        float4 w0[8], w1[8];
        {
            const float4* p0 = reinterpret_cast<const float4*>(Whh + (size_t)r0 * HDIM);
            const float4* p1 = reinterpret_cast<const float4*>(Whh + (size_t)r1 * HDIM);
#pragma unroll
            for (int j = 0; j < 8; ++j) { w0[j] = p0[j * 32 + lane]; w1[j] = p1[j * 32 + lane]; }
        }

        s_chars[tid] = chars[tid];
        reinterpret_cast<float4*>(sh)[tid] = reinterpret_cast<const float4*>(h0)[tid];
        __syncthreads();

        float bh0 = 0.f, bh1 = 0.f, px0 = 0.f, px1 = 0.f;
        if (lane == 0) {
            bh0 = bh[r0]; bh1 = bh[r1];
            const int c0 = s_chars[0];
            px0 = Wxh[(size_t)r0 * VOCAB + c0];   // prefetch x for step 0
            px1 = Wxh[(size_t)r1 * VOCAB + c0];
        }

        for (int t = 0; t < TSTEPS; ++t) {
            float x0 = px0, x1 = px1;
            if (lane == 0 && t + 1 < TSTEPS) {    // prefetch next step's x (hidden)
                const int cn = s_chars[t + 1];
                px0 = Wxh[(size_t)r0 * VOCAB + cn];
                px1 = Wxh[(size_t)r1 * VOCAB + cn];
            }

            float a0 = 0.f, a1 = 0.f;
#pragma unroll
            for (int j = 0; j < 8; ++j) {
                float4 hv = reinterpret_cast<const float4*>(sh)[j * 32 + lane];
                a0 += w0[j].x * hv.x + w0[j].y * hv.y + w0[j].z * hv.z + w0[j].w * hv.w;
                a1 += w1[j].x * hv.x + w1[j].y * hv.y + w1[j].z * hv.z + w1[j].w * hv.w;
            }
#pragma unroll
            for (int o = 16; o > 0; o >>= 1) {
                a0 += __shfl_down_sync(0xffffffffu, a0, o);
                a1 += __shfl_down_sync(0xffffffffu, a1, o);
            }

            if (lane == 0) {
                float h0v = tanhf(a0 + x0 + bh0);
                float h1v = tanhf(a1 + x1 + bh1);
                uint32_t pk = pack_bf16(h0v, h1v);
                *reinterpret_cast<uint32_t*>(g_Hb + (size_t)t * HDIM + r0) = pk;
                hout_u[wid] = pk;
            }

            if (t + 1 < TSTEPS) {
                const uint32_t tag = (uint32_t)(t + 1);
                __syncthreads();   // hout_u + g_Hb stores ordered for all threads

                if (tid < VEC_PER_BLK) {
                    const int j = tid;
                    uint4 v;
                    v.x = hout_u[3 * j];
                    v.y = hout_u[(3 * j + 1 < 8) ? 3 * j + 1 : 7];
                    v.z = hout_u[(3 * j + 2 < 8) ? 3 * j + 2 : 7];
                    v.w = tag;
                    stv4u(&g_pub[((t & 1) * NVEC + bid * VEC_PER_BLK + j) * VEC_STRIDE], v);
                }
                if (tid == THREADS - 1)
                    st_release(&g_prog[bid * 256], tag);   // release this block's h<=t

                if (tid < NVEC) {
                    const uint4* base = &g_pub[(t & 1) * NVEC * VEC_STRIDE];
                    uint4 v;
                    do { v = ldv4u(base + tid * VEC_STRIDE); } while (v.w != tag);
                    const int b = tid / VEC_PER_BLK, j = tid % VEC_PER_BLK;
                    const int bs = b * 16, w0i = 3 * j;
                    sh[bs + 2 * w0i]     = bf16lo(v.x);
                    sh[bs + 2 * w0i + 1] = bf16hi(v.x);
                    if (w0i + 1 < 8) {
                        sh[bs + 2 * w0i + 2] = bf16lo(v.y);
                        sh[bs + 2 * w0i + 3] = bf16hi(v.y);
                    }
                    if (w0i + 2 < 8) {
                        sh[bs + 2 * w0i + 4] = bf16lo(v.z);
                        sh[bs + 2 * w0i + 5] = bf16hi(v.z);
                    }
                }
                __syncthreads();
            }
        }
        __syncthreads();
        if (tid == THREADS - 1) st_release(&g_prog[bid * 256], (unsigned)TSTEPS);
    }

    // ======================= phase B: GEMM tile worker ======================
    __nv_bfloat16* ts = reinterpret_cast<__nv_bfloat16*>(smem_raw);
    const uint32_t ts_u = (uint32_t)__cvta_generic_to_shared(smem_raw);
    const int wm = wid & 3;           // 4 m-warps -> 32 vocab rows each
    const int wn = wid >> 2;          // 2 n-warps -> 32 time cols each
    const int rr = lane >> 2;
    const int cc = lane & 3;

    // B loader mapping (FIXED from R9): 64 rows x 4 chunks of 16B = 256 ops, 1/thread
    const int rowB = tid >> 2;
    const int chb  = tid & 3;

    for (;;) {
        if (tid == 0) s_q = atomicAdd(&g_qtile, 1u);
        __syncthreads();
        const unsigned q = s_q;
        if (q >= (unsigned)NTILES) break;
        const int tb = (int)(q / VBLKS);
        const int vb = (int)(q % VBLKS);
        const int m0 = vb * 128;
        const int n0 = tb * TBROWS;

        // gate: all 64 rnn blocks reached step (tb+1)*64
        if (wid == 0) {
            const unsigned T = (unsigned)((tb + 1) * TBROWS);
            for (;;) {
                unsigned va = ld_relaxed(&g_prog[lane * 256]);
                unsigned vb2 = ld_relaxed(&g_prog[(lane + 32) * 256]);
                if (__all_sync(0xffffffffu, va >= T && vb2 >= T)) break;
                __nanosleep(200);
            }
            fence_acqrel_gpu();       // acquire rnn blocks' g_Hb stores
        }
        __syncthreads();

        // ---- tile GEMM: D[128 v, 64 t], K=1024, BK=32, double-buffered
        const int rowA0 = tid >> 2;              // 0..63
        const int ch    = tid & 3;               // 8-float chunk
        const int rowA1 = rowA0 + 64;
        int gm0 = m0 + rowA0; if (gm0 > VOCAB - 1) gm0 = VOCAB - 1;
        int gm1 = m0 + rowA1; if (gm1 > VOCAB - 1) gm1 = VOCAB - 1;
        const float4* Ap0 = reinterpret_cast<const float4*>(Why + (size_t)gm0 * HDIM + ch * 8);
        const float4* Ap1 = reinterpret_cast<const float4*>(Why + (size_t)gm1 * HDIM + ch * 8);

        float4 a00 = Ap0[0], a01 = Ap0[1], a10 = Ap1[0], a11 = Ap1[1];
        {   // B stage 0 (FIXED: full 32 k-columns)
            cp16(ts_u + (uint32_t)(A_TILE + rowB * PITCH + chb * 8) * 2u,
                 g_Hb + (size_t)(n0 + rowB) * HDIM + chb * 8);
            cp_commit();
        }

        float acc[2][4][4] = {};

        for (int kt = 0; kt < HDIM / TBK; ++kt) {
            const int cur = kt & 1;
            __nv_bfloat16* As = ts + cur * STAGE;
            const __nv_bfloat16* Bs = As + A_TILE;

            {   // STS A (convert fp32->bf16)
                uint4 p;
                p.x = pack_bf16(a00.x, a00.y); p.y = pack_bf16(a00.z, a00.w);
                p.z = pack_bf16(a01.x, a01.y); p.w = pack_bf16(a01.z, a01.w);
                *reinterpret_cast<uint4*>(As + rowA0 * PITCH + ch * 8) = p;
                uint4 p2;
                p2.x = pack_bf16(a10.x, a10.y); p2.y = pack_bf16(a10.z, a10.w);
                p2.z = pack_bf16(a11.x, a11.y); p2.w = pack_bf16(a11.z, a11.w);
                *reinterpret_cast<uint4*>(As + rowA1 * PITCH + ch * 8) = p2;
            }
            if (kt + 1 < HDIM / TBK) {
                a00 = Ap0[(kt + 1) * 8];  a01 = Ap0[(kt + 1) * 8 + 1];
                a10 = Ap1[(kt + 1) * 8];  a11 = Ap1[(kt + 1) * 8 + 1];
            }
            cp_wait0();
            __syncthreads();
            if (kt + 1 < HDIM / TBK) {
                // next B stage (FIXED: full 32 k-columns)
                cp16(ts_u + (uint32_t)((cur ^ 1) * STAGE + A_TILE + rowB * PITCH + chb * 8) * 2u,
                     g_Hb + (size_t)(n0 + rowB) * HDIM + (kt + 1) * TBK + chb * 8);
                cp_commit();
            }

#pragma unroll
            for (int ki = 0; ki < 2; ++ki) {
                uint32_t afr[2][4], bfr[4][2];
                const int kk = ki * 16 + 2 * cc;
#pragma unroll
                for (int mi = 0; mi < 2; ++mi) {
                    const int mr = wm * 32 + mi * 16 + rr;
                    afr[mi][0] = *reinterpret_cast<const uint32_t*>(As + (mr    ) * PITCH + kk    );
                    afr[mi][1] = *reinterpret_cast<const uint32_t*>(As + (mr + 8) * PITCH + kk    );
                    afr[mi][2] = *reinterpret_cast<const uint32_t*>(As + (mr    ) * PITCH + kk + 8);
                    afr[mi][3] = *reinterpret_cast<const uint32_t*>(As + (mr + 8) * PITCH + kk + 8);
                }
#pragma unroll
                for (int nf = 0; nf < 4; ++nf) {
                    const int nc = wn * 32 + nf * 8 + rr;
                    bfr[nf][0] = *reinterpret_cast<const uint32_t*>(Bs + nc * PITCH + kk    );
                    bfr[nf][1] = *reinterpret_cast<const uint32_t*>(Bs + nc * PITCH + kk + 8);
                }
#pragma unroll
                for (int mi = 0; mi < 2; ++mi)
#pragma unroll
                    for (int nf = 0; nf < 4; ++nf)
                        mma_bf16(acc[mi][nf], afr[mi], bfr[nf]);
            }
        }

        // epilogue
#pragma unroll
        for (int mi = 0; mi < 2; ++mi) {
            const int v0 = m0 + wm * 32 + mi * 16 + rr;
            const int v1 = v0 + 8;
            const float bias0 = (v0 < VOCAB) ? by[v0] : 0.f;
            const float bias1 = (v1 < VOCAB) ? by[v1] : 0.f;
#pragma unroll
            for (int nf = 0; nf < 4; ++nf) {
                const int t0 = n0 + wn * 32 + nf * 8 + cc * 2;
                const int t1 = t0 + 1;
                if (v0 < VOCAB) {
                    out[(size_t)t0 * VOCAB + v0] = acc[mi][nf][0] + bias0;
                    out[(size_t)t1 * VOCAB + v0] = acc[mi][nf][1] + bias0;
                }
                if (v1 < VOCAB) {
                    out[(size_t)t0 * VOCAB + v1] = acc[mi][nf][2] + bias1;
                    out[(size_t)t1 * VOCAB + v1] = acc[mi][nf][3] + bias1;
                }
            }
        }

        __syncthreads();               // all STGs issued
        if (tid == 0) red_release_add(&g_done[tb * 256], 1u);
    }

    // ======================= phase C: softmax rows ==========================
    float* sexp = reinterpret_cast<float*>(smem_raw);
    for (;;) {
        if (tid == 0) s_q = atomicAdd(&g_qrow, 1u);
        __syncthreads();
        const unsigned r = s_q;
        __syncthreads();
        if (r >= (unsigned)TSTEPS) break;
        const int tb = (int)(r / TBROWS);

        if (tid == 0) {
            while (ld_relaxed(&g_done[tb * 256]) < (unsigned)VBLKS) __nanosleep(300);
            fence_acqrel_gpu();
        }
        __syncthreads();

        float* rowp = out + (size_t)r * VOCAB;

        float m = -1e30f;
        for (int i = tid; i < VOCAB; i += THREADS) m = fmaxf(m, rowp[i]);
        red2[tid] = m; __syncthreads();
        for (int s = THREADS / 2; s > 0; s >>= 1) {
            if (tid < s) red2[tid] = fmaxf(red2[tid], red2[tid + s]);
            __syncthreads();
        }
        m = red2[0];
        __syncthreads();

        float sum = 0.f;
        for (int i = tid; i < VOCAB; i += THREADS) {
            float e = expf(rowp[i] - m);
            sexp[i] = e;
            sum += e;
        }
        red2[tid] = sum; __syncthreads();
        for (int s = THREADS / 2; s > 0; s >>= 1) {
            if (tid < s) red2[tid] += red2[tid + s];
            __syncthreads();
        }
        const float inv = 1.0f / red2[0];
        __syncthreads();

        for (int i = tid; i < VOCAB; i += THREADS) rowp[i] = sexp[i] * inv;
        __syncthreads();
    }
}

// ---------------- launch ----------------
extern "C" void kernel_launch(void* const* d_in, const int* in_sizes, int n_in,
                              void* d_out, int out_size) {
    const int*   chars = (const int*)  d_in[0];
    const float* Wxh   = (const float*)d_in[1];
    const float* Whh   = (const float*)d_in[2];
    const float* Why   = (const float*)d_in[3];
    const float* bh    = (const float*)d_in[4];
    const float* by    = (const float*)d_in[5];
    const float* h0    = (const float*)d_in[6];
    float* out = (float*)d_out;

    cudaFuncSetAttribute(fused_kernel,
                         cudaFuncAttributeMaxDynamicSharedMemorySize, FUSED_SMEM_BYTES);

    init_kernel<<<1, 1024>>>();
    fused_kernel<<<GRID_CTAS, THREADS, FUSED_SMEM_BYTES>>>(chars, Wxh, Whh, Why, bh, by, h0, out);
}

// round 11
// speedup vs baseline: 1.0837x; 1.0837x over previous
#include <cuda_runtime.h>
#include <cuda_bf16.h>
#include <math.h>
#include <stdint.h>

#define HDIM   1024
#define TSTEPS 256
#define VOCAB  50257

// ---------------- recurrence config (R8 WIN + folded gather) ----------------
#define RNN_NB      64
#define RNN_THREADS 256
#define VEC_PER_BLK 3
#define NVEC        (RNN_NB * VEC_PER_BLK)   // 192
#define VEC_STRIDE  8                        // 128B per vector

// -------- device scratch --------
__device__ __align__(16)  __nv_bfloat16 g_Hb[TSTEPS * HDIM];
__device__ __align__(128) uint4 g_pub[2 * NVEC * VEC_STRIDE];

// ---- asm helpers
__device__ __forceinline__ uint4 ldv4u(const uint4* p) {
    uint4 v;
    asm volatile("ld.volatile.global.v4.u32 {%0,%1,%2,%3}, [%4];"
                 : "=r"(v.x), "=r"(v.y), "=r"(v.z), "=r"(v.w) : "l"(p));
    return v;
}
__device__ __forceinline__ void stv4u(uint4* p, uint4 v) {
    asm volatile("st.volatile.global.v4.u32 [%0], {%1,%2,%3,%4};"
                 :: "l"(p), "r"(v.x), "r"(v.y), "r"(v.z), "r"(v.w) : "memory");
}
__device__ __forceinline__ uint32_t pack_bf16(float lo, float hi) {
    __nv_bfloat162 v = __floats2bfloat162_rn(lo, hi);
    return *reinterpret_cast<uint32_t*>(&v);
}
__device__ __forceinline__ float bf16lo(uint32_t u) { return __uint_as_float(u << 16); }
__device__ __forceinline__ float bf16hi(uint32_t u) { return __uint_as_float(u & 0xFFFF0000u); }
__device__ __forceinline__ void cp16(uint32_t sdst, const void* gsrc) {
    asm volatile("cp.async.cg.shared.global [%0], [%1], 16;\n" :: "r"(sdst), "l"(gsrc));
}
__device__ __forceinline__ void cp_commit() { asm volatile("cp.async.commit_group;\n"); }
__device__ __forceinline__ void cp_wait0()  { asm volatile("cp.async.wait_group 0;\n"); }
__device__ __forceinline__ void mma_bf16(float d[4], const uint32_t a[4], const uint32_t b[2]) {
    asm volatile(
        "mma.sync.aligned.m16n8k16.row.col.f32.bf16.bf16.f32 "
        "{%0,%1,%2,%3}, {%4,%5,%6,%7}, {%8,%9}, {%0,%1,%2,%3};\n"
        : "+f"(d[0]), "+f"(d[1]), "+f"(d[2]), "+f"(d[3])
        : "r"(a[0]), "r"(a[1]), "r"(a[2]), "r"(a[3]), "r"(b[0]), "r"(b[1]));
}
__device__ __forceinline__ void ldsm_x4(uint32_t& r0, uint32_t& r1, uint32_t& r2, uint32_t& r3,
                                        uint32_t saddr) {
    asm volatile("ldmatrix.sync.aligned.m8n8.x4.shared.b16 {%0,%1,%2,%3}, [%4];"
                 : "=r"(r0), "=r"(r1), "=r"(r2), "=r"(r3) : "r"(saddr));
}

// ---------------- init: clear exchange tags each launch (graph-replay determinism)
__global__ void init_kernel() {
    int i = blockIdx.x * blockDim.x + threadIdx.x;
    if (i < 2 * NVEC) g_pub[i * VEC_STRIDE].w = 0u;
}

// ---------------- phase 1: recurrence, fence-free tagged exchange, gather folded.
// 64 blocks x 8 warps, 2 rows/warp; x_t = Wxh[row][c_t] prefetched one step ahead.
__global__ void __launch_bounds__(RNN_THREADS, 1)
rnn_steps_kernel(const int* __restrict__ chars,
                 const float* __restrict__ Wxh,
                 const float* __restrict__ Whh,
                 const float* __restrict__ bh,
                 const float* __restrict__ h0) {
    __shared__ float    sh[HDIM];
    __shared__ uint32_t hout_u[8];
    __shared__ int      s_chars[TSTEPS];

    const int tid  = threadIdx.x;
    const int wid  = tid >> 5;
    const int lane = tid & 31;
    const int r0   = blockIdx.x * 16 + wid * 2;
    const int r1   = r0 + 1;

    float4 w0[8], w1[8];
    {
        const float4* p0 = reinterpret_cast<const float4*>(Whh + (size_t)r0 * HDIM);
        const float4* p1 = reinterpret_cast<const float4*>(Whh + (size_t)r1 * HDIM);
#pragma unroll
        for (int j = 0; j < 8; ++j) { w0[j] = p0[j * 32 + lane]; w1[j] = p1[j * 32 + lane]; }
    }

    s_chars[tid] = chars[tid];
    reinterpret_cast<float4*>(sh)[tid] = reinterpret_cast<const float4*>(h0)[tid];
    __syncthreads();

    float bh0 = 0.f, bh1 = 0.f, px0 = 0.f, px1 = 0.f;
    if (lane == 0) {
        bh0 = bh[r0]; bh1 = bh[r1];
        const int c0 = s_chars[0];
        px0 = Wxh[(size_t)r0 * VOCAB + c0];
        px1 = Wxh[(size_t)r1 * VOCAB + c0];
    }

    for (int t = 0; t < TSTEPS; ++t) {
        float x0 = px0, x1 = px1;
        if (lane == 0 && t + 1 < TSTEPS) {
            const int cn = s_chars[t + 1];
            px0 = Wxh[(size_t)r0 * VOCAB + cn];
            px1 = Wxh[(size_t)r1 * VOCAB + cn];
        }

        float a0 = 0.f, a1 = 0.f;
#pragma unroll
        for (int j = 0; j < 8; ++j) {
            float4 hv = reinterpret_cast<const float4*>(sh)[j * 32 + lane];
            a0 += w0[j].x * hv.x + w0[j].y * hv.y + w0[j].z * hv.z + w0[j].w * hv.w;
            a1 += w1[j].x * hv.x + w1[j].y * hv.y + w1[j].z * hv.z + w1[j].w * hv.w;
        }
#pragma unroll
        for (int o = 16; o > 0; o >>= 1) {
            a0 += __shfl_down_sync(0xffffffffu, a0, o);
            a1 += __shfl_down_sync(0xffffffffu, a1, o);
        }

        if (lane == 0) {
            float h0v = tanhf(a0 + x0 + bh0);
            float h1v = tanhf(a1 + x1 + bh1);
            uint32_t pk = pack_bf16(h0v, h1v);
            *reinterpret_cast<uint32_t*>(g_Hb + (size_t)t * HDIM + r0) = pk;
            hout_u[wid] = pk;
        }

        if (t + 1 < TSTEPS) {
            const uint32_t tag = (uint32_t)(t + 1);
            __syncthreads();

            if (tid < VEC_PER_BLK) {
                const int j = tid;
                uint4 v;
                v.x = hout_u[3 * j];
                v.y = hout_u[(3 * j + 1 < 8) ? 3 * j + 1 : 7];
                v.z = hout_u[(3 * j + 2 < 8) ? 3 * j + 2 : 7];
                v.w = tag;
                stv4u(&g_pub[((t & 1) * NVEC + blockIdx.x * VEC_PER_BLK + j) * VEC_STRIDE], v);
            }

            if (tid < NVEC) {
                const uint4* base = &g_pub[(t & 1) * NVEC * VEC_STRIDE];
                uint4 v;
                do { v = ldv4u(base + tid * VEC_STRIDE); } while (v.w != tag);
                const int b = tid / VEC_PER_BLK, j = tid % VEC_PER_BLK;
                const int bs = b * 16, w0i = 3 * j;
                sh[bs + 2 * w0i]     = bf16lo(v.x);
                sh[bs + 2 * w0i + 1] = bf16hi(v.x);
                if (w0i + 1 < 8) {
                    sh[bs + 2 * w0i + 2] = bf16lo(v.y);
                    sh[bs + 2 * w0i + 3] = bf16hi(v.y);
                }
                if (w0i + 2 < 8) {
                    sh[bs + 2 * w0i + 4] = bf16lo(v.z);
                    sh[bs + 2 * w0i + 5] = bf16hi(v.z);
                }
            }
            __syncthreads();
        }
    }
}

// ---------------- phase 2: bf16 mma.sync GEMM with ldmatrix fragments
// logits[t][v] = sum_k Why[v][k] * H[t][k] + by[v]
#define BM 128
#define BN 256
#define BK 32
#define GEMM_THREADS 512
#define PITCH_H 40                            // 80B rows: ldmatrix conflict-free, 16B aligned
#define A_TILE_H (BM * PITCH_H)
#define B_TILE_H (BN * PITCH_H)
#define STAGE_H  (A_TILE_H + B_TILE_H)
#define GEMM_SMEM_BYTES (2 * STAGE_H * 2)     // 61440 B

extern __shared__ __nv_bfloat16 g_smem[];

__global__ void __launch_bounds__(GEMM_THREADS, 1)
gemm_logits_kernel(const float* __restrict__ Why,
                   const float* __restrict__ by,
                   float* __restrict__ out) {
    const int tid  = threadIdx.x;
    const int lane = tid & 31;
    const int wid  = tid >> 5;
    const int wm   = wid & 3;        // warp m (0..3) -> 32 vocab rows
    const int wn   = wid >> 2;       // warp n (0..3) -> 64 time cols
    const int m0   = blockIdx.x * BM;

    const uint32_t smem_u = (uint32_t)__cvta_generic_to_shared(g_smem);

    // A (Why) LDG mapping: thread -> (row, k-chunk of 8 fp32)
    const int arow = tid >> 2;
    const int ak0  = (tid & 3) * 8;
    int agm = m0 + arow; if (agm > VOCAB - 1) agm = VOCAB - 1;
    const float4* Aptr = reinterpret_cast<const float4*>(Why + (size_t)agm * HDIM + ak0);

    auto load_B = [&](int stage, int k0) {
        uint32_t sb = smem_u + (uint32_t)(stage * STAGE_H + A_TILE_H) * 2u;
#pragma unroll
        for (int q = 0; q < 2; ++q) {
            int i = tid + q * GEMM_THREADS;
            int row = i >> 2, ch = i & 3;
            cp16(sb + (uint32_t)(row * PITCH_H + ch * 8) * 2u,
                 g_Hb + (size_t)row * HDIM + k0 + ch * 8);
        }
        cp_commit();
    };

    float acc[2][8][4] = {};

    float4 fa = Aptr[0];
    float4 fb = Aptr[1];
    load_B(0, 0);

    // ldmatrix per-lane row/col selectors
    const int lra = lane & 15;                 // A: rows 0..15 within m16
    const int lca = (lane >> 4) * 8;           // A: k offset 0/8
    const int lrb = (lane & 7) + ((lane >> 4) * 8);   // B: n row within n16
    const int lcb = ((lane >> 3) & 1) * 8;     // B: k offset 0/8

    for (int kt = 0; kt < HDIM / BK; ++kt) {
        const int cur = kt & 1;
        __nv_bfloat16* As = g_smem + cur * STAGE_H;
        const uint32_t As_u = smem_u + (uint32_t)(cur * STAGE_H) * 2u;
        const uint32_t Bs_u = As_u + (uint32_t)A_TILE_H * 2u;

        {   // STS this kt's A (one STS.128)
            uint4 p;
            p.x = pack_bf16(fa.x, fa.y);
            p.y = pack_bf16(fa.z, fa.w);
            p.z = pack_bf16(fb.x, fb.y);
            p.w = pack_bf16(fb.z, fb.w);
            *reinterpret_cast<uint4*>(As + arow * PITCH_H + ak0) = p;
        }
        if (kt + 1 < HDIM / BK) {
            const float4* An = Aptr + (kt + 1) * (BK / 4);
            fa = An[0];
            fb = An[1];
        }

        cp_wait0();
        __syncthreads();

        if (kt + 1 < HDIM / BK)
            load_B(cur ^ 1, (kt + 1) * BK);

#pragma unroll
        for (int ki = 0; ki < 2; ++ki) {
            const int kk = ki * 16;
            uint32_t a[2][4], b[8][2];
#pragma unroll
            for (int mi = 0; mi < 2; ++mi)
                ldsm_x4(a[mi][0], a[mi][1], a[mi][2], a[mi][3],
                        As_u + (uint32_t)((wm * 32 + mi * 16 + lra) * PITCH_H + kk + lca) * 2u);
#pragma unroll
            for (int nf2 = 0; nf2 < 4; ++nf2)
                ldsm_x4(b[2 * nf2][0], b[2 * nf2][1], b[2 * nf2 + 1][0], b[2 * nf2 + 1][1],
                        Bs_u + (uint32_t)((wn * 64 + nf2 * 16 + lrb) * PITCH_H + kk + lcb) * 2u);
#pragma unroll
            for (int mi = 0; mi < 2; ++mi)
#pragma unroll
                for (int nf = 0; nf < 8; ++nf)
                    mma_bf16(acc[mi][nf], a[mi], b[nf]);
        }
    }

    // ---- epilogue: out[t][v] = acc + by[v]
    const int r = lane >> 2;
    const int c = lane & 3;
#pragma unroll
    for (int mi = 0; mi < 2; ++mi) {
        const int v0 = m0 + wm * 32 + mi * 16 + r;
        const int v1 = v0 + 8;
        const float bias0 = (v0 < VOCAB) ? by[v0] : 0.f;
        const float bias1 = (v1 < VOCAB) ? by[v1] : 0.f;
#pragma unroll
        for (int nf = 0; nf < 8; ++nf) {
            const int t0 = wn * 64 + nf * 8 + c * 2;
            const int t1 = t0 + 1;
            if (v0 < VOCAB) {
                out[(size_t)t0 * VOCAB + v0] = acc[mi][nf][0] + bias0;
                out[(size_t)t1 * VOCAB + v0] = acc[mi][nf][1] + bias0;
            }
            if (v1 < VOCAB) {
                out[(size_t)t0 * VOCAB + v1] = acc[mi][nf][2] + bias1;
                out[(size_t)t1 * VOCAB + v1] = acc[mi][nf][3] + bias1;
            }
        }
    }
}

// ---------------- phase 3: softmax with smem exp cache
#define SMAX_SMEM_BYTES (VOCAB * 4)

extern __shared__ float s_exp[];

__global__ void __launch_bounds__(1024) softmax_rows_kernel(float* __restrict__ out) {
    __shared__ float red[1024];
    const int t = blockIdx.x;
    float* row = out + (size_t)t * VOCAB;
    const int tid = threadIdx.x;

    float m = -1e30f;
    for (int i = tid; i < VOCAB; i += 1024) m = fmaxf(m, row[i]);
    red[tid] = m; __syncthreads();
    for (int s = 512; s > 0; s >>= 1) {
        if (tid < s) red[tid] = fmaxf(red[tid], red[tid + s]);
        __syncthreads();
    }
    m = red[0];
    __syncthreads();

    float sum = 0.f;
    for (int i = tid; i < VOCAB; i += 1024) {
        float e = expf(row[i] - m);
        s_exp[i] = e;
        sum += e;
    }
    red[tid] = sum; __syncthreads();
    for (int s = 512; s > 0; s >>= 1) {
        if (tid < s) red[tid] += red[tid + s];
        __syncthreads();
    }
    float inv = 1.0f / red[0];
    __syncthreads();

    for (int i = tid; i < VOCAB; i += 1024) row[i] = s_exp[i] * inv;
}

// ---------------- launch ----------------
extern "C" void kernel_launch(void* const* d_in, const int* in_sizes, int n_in,
                              void* d_out, int out_size) {
    const int*   chars = (const int*)  d_in[0];
    const float* Wxh   = (const float*)d_in[1];
    const float* Whh   = (const float*)d_in[2];
    const float* Why   = (const float*)d_in[3];
    const float* bh    = (const float*)d_in[4];
    const float* by    = (const float*)d_in[5];
    const float* h0    = (const float*)d_in[6];
    float* out = (float*)d_out;

    cudaFuncSetAttribute(gemm_logits_kernel,
                         cudaFuncAttributeMaxDynamicSharedMemorySize, GEMM_SMEM_BYTES);
    cudaFuncSetAttribute(softmax_rows_kernel,
                         cudaFuncAttributeMaxDynamicSharedMemorySize, SMAX_SMEM_BYTES);

    init_kernel<<<1, 512>>>();
    rnn_steps_kernel<<<RNN_NB, RNN_THREADS>>>(chars, Wxh, Whh, bh, h0);
    gemm_logits_kernel<<<(VOCAB + BM - 1) / BM, GEMM_THREADS, GEMM_SMEM_BYTES>>>(Why, by, out);
    softmax_rows_kernel<<<TSTEPS, 1024, SMAX_SMEM_BYTES>>>(out);
}